// round 6
// baseline (speedup 1.0000x reference)
#include <cuda_runtime.h>
#include <math.h>
#include <stdint.h>

#define NN 100000
#define NE 3200000
#define MAXD 256

typedef unsigned long long ull;

// ---------------- static device scratch (allocation-free contract) ----------------
__device__ float g_bufA[(size_t)NN * MAXD];
__device__ float g_bufB[(size_t)NN * MAXD];
__device__ float g_bufC[(size_t)NN * MAXD];
__device__ int   g_src[NE];
__device__ int   g_dst[NE];
__device__ int   g_cnt[NN];        // invariant: zero at entry of kernel_launch
__device__ int   g_rowptr[NN + 1];
__device__ int   g_woff[NN];
__device__ int2  g_csre[NE];       // packed {src, weight-bits}
__device__ float g_di[NN];
__device__ float g_dis[NN];
__device__ float g_bn[512];        // invariant: zero at entry (finalize re-zeroes)
__device__ float g_scale[256];
__device__ float g_shift[256];

// packed f32x2 FMA: d = a*b + d (elementwise on 2 packed floats)
__device__ __forceinline__ void ffma2(ull& d, ull a, ull b) {
    asm("fma.rn.f32x2 %0, %1, %2, %0;" : "+l"(d) : "l"(a), "l"(b));
}
union U4 { float4 v; ull u[2]; float f[4]; };

// ---------------- prep: detect dtype inline, convert, count in-degree ----------------
__global__ void k_prep_edges(const void* __restrict__ ei_raw,
                             int* __restrict__ src, int* __restrict__ dst,
                             int* __restrict__ cnt, int E, int n) {
    const unsigned int* w = (const unsigned int*)ei_raw;
    unsigned int probe = w[2 * (threadIdx.x & 255) + 1];
    int any = __syncthreads_or(probe != 0u);
    const int is64 = (any == 0);
    const long long* ei64 = (const long long*)ei_raw;
    const int* ei32 = (const int*)ei_raw;
    for (int e = blockIdx.x * blockDim.x + threadIdx.x; e < E; e += gridDim.x * blockDim.x) {
        int s, d;
        if (is64) { s = (int)ei64[e]; d = (int)ei64[(size_t)E + e]; }
        else      { s = ei32[e];      d = ei32[(size_t)E + e]; }
        if ((unsigned)s >= (unsigned)n) s = 0;
        if ((unsigned)d >= (unsigned)n) d = 0;
        src[e] = s;
        dst[e] = d;
        atomicAdd(&cnt[d], 1);
    }
}

// ---------------- single-block tiled coalesced scan + deg + cnt re-zero ----------------
__global__ void k_scan_deg(int* __restrict__ cnt, int* __restrict__ rowptr,
                           int* __restrict__ woff, float* __restrict__ di,
                           float* __restrict__ dis, int n) {
    __shared__ int wsum[32];
    __shared__ int s_off;
    int t = threadIdx.x, lane = t & 31, wid = t >> 5;
    if (t == 0) s_off = 0;
    __syncthreads();
    for (int base = 0; base < n; base += 1024) {
        int i = base + t;
        int c = (i < n) ? cnt[i] : 0;
        if (i < n) cnt[i] = 0;
        int x = c;
#pragma unroll
        for (int o = 1; o < 32; o <<= 1) {
            int v = __shfl_up_sync(0xffffffffu, x, o);
            if (lane >= o) x += v;
        }
        if (lane == 31) wsum[wid] = x;
        __syncthreads();
        if (wid == 0) {
            int y = wsum[lane];
#pragma unroll
            for (int o = 1; o < 32; o <<= 1) {
                int v = __shfl_up_sync(0xffffffffu, y, o);
                if (lane >= o) y += v;
            }
            wsum[lane] = y;
        }
        __syncthreads();
        int wbase = (wid == 0) ? 0 : wsum[wid - 1];
        int excl = x + wbase - c;
        int off0 = s_off;
        if (i < n) {
            int r = off0 + excl;
            rowptr[i] = r;
            woff[i]   = r;
            float dg = (float)c + 1.0f;
            di[i]  = 1.0f / dg;
            dis[i] = rsqrtf(dg);
        }
        __syncthreads();
        if (t == 1023) s_off = off0 + wsum[31];
        __syncthreads();
    }
    if (t == 0) rowptr[n] = s_off;
}

// ---------------- CSR scatter with packed (src, weight) ----------------
__global__ void k_csr(const int* __restrict__ src, const int* __restrict__ dst,
                      const float* __restrict__ dis, int* __restrict__ woff,
                      int2* __restrict__ csre, int E) {
    for (int e = blockIdx.x * blockDim.x + threadIdx.x; e < E; e += gridDim.x * blockDim.x) {
        int d = dst[e];
        int pos = atomicAdd(&woff[d], 1);
        int s = src[e];
        if (pos < E) {
            float w = dis[s] * dis[d];
            csre[pos] = make_int2(s, __float_as_int(w));
        }
    }
}

// ---------------- aggregation: warp-per-node gather (R3-proven 2-edge unroll) ----------------
template <int D, bool EPI, bool AFF>
__global__ __launch_bounds__(256) void k_agg(
    const float* __restrict__ xin, float* __restrict__ xout,
    const int* __restrict__ rowptr, const int2* __restrict__ csre,
    const float* __restrict__ di, int n,
    const float* __restrict__ scale, const float* __restrict__ shift,
    const float* __restrict__ bias, float* __restrict__ bnsum, float* __restrict__ bnsq)
{
    constexpr int CPL = D / 32;
    int lane = threadIdx.x & 31;
    int node = blockIdx.x * 8 + (threadIdx.x >> 5);
    float acc[CPL];
    float sc[CPL], sh[CPL];
#pragma unroll
    for (int j = 0; j < CPL; j++) {
        acc[j] = 0.f;
        if (AFF) { sc[j] = scale[lane + 32 * j]; sh[j] = shift[lane + 32 * j]; }
    }

    if (node < n) {
        int beg = rowptr[node], end = rowptr[node + 1];
        int e = beg;
        for (; e + 2 <= end; e += 2) {
            int2 p0 = __ldg(&csre[e]);
            int2 p1 = __ldg(&csre[e + 1]);
            float w0 = __int_as_float(p0.y);
            float w1 = __int_as_float(p1.y);
            const float* r0 = xin + (size_t)p0.x * D + lane;
            const float* r1 = xin + (size_t)p1.x * D + lane;
            float v0[CPL], v1[CPL];
#pragma unroll
            for (int j = 0; j < CPL; j++) v0[j] = __ldg(r0 + 32 * j);
#pragma unroll
            for (int j = 0; j < CPL; j++) v1[j] = __ldg(r1 + 32 * j);
#pragma unroll
            for (int j = 0; j < CPL; j++) {
                float a0 = AFF ? fmaxf(v0[j] * sc[j] + sh[j], 0.f) : v0[j];
                float a1 = AFF ? fmaxf(v1[j] * sc[j] + sh[j], 0.f) : v1[j];
                acc[j] += w0 * a0;
                acc[j] += w1 * a1;
            }
        }
        if (e < end) {
            int2 p0 = __ldg(&csre[e]);
            float w0 = __int_as_float(p0.y);
            const float* r0 = xin + (size_t)p0.x * D + lane;
#pragma unroll
            for (int j = 0; j < CPL; j++) {
                float v = __ldg(r0 + 32 * j);
                float a = AFF ? fmaxf(v * sc[j] + sh[j], 0.f) : v;
                acc[j] += w0 * a;
            }
        }
        float dii = di[node];
        const float* r = xin + (size_t)node * D + lane;
#pragma unroll
        for (int j = 0; j < CPL; j++) {
            float v = __ldg(r + 32 * j);
            float a = AFF ? fmaxf(v * sc[j] + sh[j], 0.f) : v;
            acc[j] += dii * a;
            if (EPI) acc[j] += bias[lane + 32 * j];
            xout[(size_t)node * D + lane + 32 * j] = acc[j];
        }
    }
    if constexpr (EPI) {
        __shared__ float csum[D];
        __shared__ float csq[D];
        for (int t = threadIdx.x; t < D; t += blockDim.x) { csum[t] = 0.f; csq[t] = 0.f; }
        __syncthreads();
        if (node < n) {
#pragma unroll
            for (int j = 0; j < CPL; j++) {
                atomicAdd(&csum[lane + 32 * j], acc[j]);
                atomicAdd(&csq[lane + 32 * j], acc[j] * acc[j]);
            }
        }
        __syncthreads();
        for (int t = threadIdx.x; t < D; t += blockDim.x) {
            atomicAdd(&bnsum[t], csum[t]);
            atomicAdd(&bnsq[t], csq[t]);
        }
    }
}

// ---------------- GEMM via packed f32x2 FMA: C = act(A)@W (+bias, BN stats) ----------------
// 128x64 tile; micro 8(row-pairs=4 f32x2) x 4 cols; B staged duplicated (w,w).
template <bool EPI, bool AFF>
__global__ __launch_bounds__(256) void k_gemm(
    const float* __restrict__ A, const float* __restrict__ W, float* __restrict__ C,
    int M, int K, int Nc,
    const float* __restrict__ scale, const float* __restrict__ shift,
    const float* __restrict__ bias, float* __restrict__ bnsum, float* __restrict__ bnsq)
{
    __shared__ float  As[16][128];
    __shared__ float2 Bs[16][64];      // duplicated (w,w)
    int tid = threadIdx.x;
    int tx = tid & 15;          // 16 col groups of 4
    int ty = tid >> 4;          // 16 row groups of 8 (4 pairs)
    int row0 = blockIdx.y * 128;
    int col0 = blockIdx.x * 64;

    ull acc[4][4];              // [row-pair][col]; .lo=row 2p, .hi=row 2p+1
#pragma unroll
    for (int p = 0; p < 4; p++)
#pragma unroll
        for (int j = 0; j < 4; j++) acc[p][j] = 0ull;

    int arow = tid >> 2;        // 0..63 (+64 for t=1)
    int afc  = tid & 3;         // float4 index along K-chunk
    int bkr  = tid >> 4;        // 0..15
    int bfc  = tid & 15;        // 0..15 float4 along 64 cols

    for (int k0 = 0; k0 < K; k0 += 16) {
        // A tile: 128 rows x 16 k, float4 along K, transposed into As[k][m] (fused act)
#pragma unroll
        for (int t = 0; t < 2; t++) {
            int m = arow + 64 * t;
            int gm = row0 + m;
            float4 v = make_float4(0.f, 0.f, 0.f, 0.f);
            if (gm < M) v = *(const float4*)(A + (size_t)gm * K + k0 + 4 * afc);
            if (AFF) {
                int kk4 = k0 + 4 * afc;
                float4 s4 = *(const float4*)(scale + kk4);
                float4 h4 = *(const float4*)(shift + kk4);
                v.x = fmaxf(v.x * s4.x + h4.x, 0.f);
                v.y = fmaxf(v.y * s4.y + h4.y, 0.f);
                v.z = fmaxf(v.z * s4.z + h4.z, 0.f);
                v.w = fmaxf(v.w * s4.w + h4.w, 0.f);
            }
            As[4 * afc + 0][m] = v.x;
            As[4 * afc + 1][m] = v.y;
            As[4 * afc + 2][m] = v.z;
            As[4 * afc + 3][m] = v.w;
        }
        // B tile: 16 k x 64 cols, duplicated pairs
        {
            float4 v = make_float4(0.f, 0.f, 0.f, 0.f);
            int gc = col0 + 4 * bfc;
            if (gc < Nc) v = *(const float4*)(W + (size_t)(k0 + bkr) * Nc + gc);
            Bs[bkr][4 * bfc + 0] = make_float2(v.x, v.x);
            Bs[bkr][4 * bfc + 1] = make_float2(v.y, v.y);
            Bs[bkr][4 * bfc + 2] = make_float2(v.z, v.z);
            Bs[bkr][4 * bfc + 3] = make_float2(v.w, v.w);
        }
        __syncthreads();
#pragma unroll
        for (int kk = 0; kk < 16; kk++) {
            U4 a0, a1, b0, b1;
            a0.v = *(const float4*)&As[kk][ty * 8];
            a1.v = *(const float4*)&As[kk][ty * 8 + 4];
            b0.v = *(const float4*)&Bs[kk][tx * 4];
            b1.v = *(const float4*)&Bs[kk][tx * 4 + 2];
            ull ap0 = a0.u[0], ap1 = a0.u[1], ap2 = a1.u[0], ap3 = a1.u[1];
            ull bp0 = b0.u[0], bp1 = b0.u[1], bp2 = b1.u[0], bp3 = b1.u[1];
            ffma2(acc[0][0], ap0, bp0); ffma2(acc[0][1], ap0, bp1);
            ffma2(acc[0][2], ap0, bp2); ffma2(acc[0][3], ap0, bp3);
            ffma2(acc[1][0], ap1, bp0); ffma2(acc[1][1], ap1, bp1);
            ffma2(acc[1][2], ap1, bp2); ffma2(acc[1][3], ap1, bp3);
            ffma2(acc[2][0], ap2, bp0); ffma2(acc[2][1], ap2, bp1);
            ffma2(acc[2][2], ap2, bp2); ffma2(acc[2][3], ap2, bp3);
            ffma2(acc[3][0], ap3, bp0); ffma2(acc[3][1], ap3, bp1);
            ffma2(acc[3][2], ap3, bp2); ffma2(acc[3][3], ap3, bp3);
        }
        __syncthreads();
    }

    int colbase = col0 + tx * 4;
    bool colok = colbase < Nc;

    if constexpr (!EPI) {
#pragma unroll
        for (int p = 0; p < 4; p++) {
#pragma unroll
            for (int h = 0; h < 2; h++) {
                int row = row0 + ty * 8 + 2 * p + h;
                if (row < M && colok) {
                    float4 o;
                    o.x = ((float2*)&acc[p][0])[0].x * 0.f + (h ? ((float2*)&acc[p][0])->y
                                                                : ((float2*)&acc[p][0])->x);
                    // (written explicitly below to avoid confusion)
                    float2 c0 = *(float2*)&acc[p][0];
                    float2 c1 = *(float2*)&acc[p][1];
                    float2 c2 = *(float2*)&acc[p][2];
                    float2 c3 = *(float2*)&acc[p][3];
                    o.x = h ? c0.y : c0.x;
                    o.y = h ? c1.y : c1.x;
                    o.z = h ? c2.y : c2.x;
                    o.w = h ? c3.y : c3.x;
                    *(float4*)(C + (size_t)row * Nc + colbase) = o;
                }
            }
        }
    } else {
        __shared__ float csum[64];
        __shared__ float csq[64];
        if (tid < 64) { csum[tid] = 0.f; csq[tid] = 0.f; }
        __syncthreads();
        float4 b4 = colok ? *(const float4*)(bias + colbase) : make_float4(0.f, 0.f, 0.f, 0.f);
        float tsum[4] = {0.f, 0.f, 0.f, 0.f};
        float tsq[4]  = {0.f, 0.f, 0.f, 0.f};
#pragma unroll
        for (int p = 0; p < 4; p++) {
            float2 c0 = *(float2*)&acc[p][0];
            float2 c1 = *(float2*)&acc[p][1];
            float2 c2 = *(float2*)&acc[p][2];
            float2 c3 = *(float2*)&acc[p][3];
#pragma unroll
            for (int h = 0; h < 2; h++) {
                int row = row0 + ty * 8 + 2 * p + h;
                if (row < M && colok) {
                    float v0 = (h ? c0.y : c0.x) + b4.x;
                    float v1 = (h ? c1.y : c1.x) + b4.y;
                    float v2 = (h ? c2.y : c2.x) + b4.z;
                    float v3 = (h ? c3.y : c3.x) + b4.w;
                    *(float4*)(C + (size_t)row * Nc + colbase) = make_float4(v0, v1, v2, v3);
                    tsum[0] += v0; tsum[1] += v1; tsum[2] += v2; tsum[3] += v3;
                    tsq[0] += v0 * v0; tsq[1] += v1 * v1; tsq[2] += v2 * v2; tsq[3] += v3 * v3;
                }
            }
        }
#pragma unroll
        for (int j = 0; j < 4; j++) {
            atomicAdd(&csum[tx * 4 + j], tsum[j]);
            atomicAdd(&csq[tx * 4 + j], tsq[j]);
        }
        __syncthreads();
        if (tid < 64 && col0 + tid < Nc) {
            atomicAdd(&bnsum[col0 + tid], csum[tid]);
            atomicAdd(&bnsq[col0 + tid], csq[tid]);
        }
    }
}

// ---------------- BN finalize: scale/shift from stats, then re-zero stats ----------------
__global__ void k_bn_finalize(const float* __restrict__ g, const float* __restrict__ be,
                              int d, float invN, float* __restrict__ bn,
                              float* __restrict__ scale, float* __restrict__ shift) {
    int t = threadIdx.x;
    float s = bn[t], q = bn[256 + t];
    if (t < d) {
        float mu  = s * invN;
        float var = q * invN - mu * mu;
        float rstd = rsqrtf(fmaxf(var, 0.f) + 1e-5f);
        float sc = g[t] * rstd;
        scale[t] = sc;
        shift[t] = be[t] - mu * sc;
    }
    bn[t] = 0.f;
    bn[256 + t] = 0.f;
}

// ---------------- edge head: 2 edges per warp, fused affine+relu ----------------
__global__ __launch_bounds__(256) void k_edge_out(
    const float* __restrict__ conv, const int* __restrict__ src, const int* __restrict__ dst,
    const float* __restrict__ scale, const float* __restrict__ shift,
    const float* __restrict__ fcw, const float* __restrict__ fcb,
    float* __restrict__ out, int E)
{
    int warp = (blockIdx.x * blockDim.x + threadIdx.x) >> 5;
    int lane = threadIdx.x & 31;
    int half = lane >> 4;
    int l16  = lane & 15;
    int eid = warp * 2 + half;
    if (eid >= E) return;
    int s = src[eid], d = dst[eid];
    const float* rs = conv + (size_t)s * 32;
    const float* rd = conv + (size_t)d * 32;
    float v = 0.f;
#pragma unroll
    for (int p = 0; p < 2; p++) {
        int f = l16 + 16 * p;
        float sc = scale[f], sh = shift[f];
        float a = fmaxf(__ldg(rs + f) * sc + sh, 0.f);
        float b = fmaxf(__ldg(rd + f) * sc + sh, 0.f);
        v += a * b * fcw[f];
    }
#pragma unroll
    for (int o = 8; o; o >>= 1) v += __shfl_xor_sync(0xffffffffu, v, o);
    if (l16 == 0) out[eid] = 1.f / (1.f + expf(-(v + fcb[0])));
}

// ---------------- host ----------------
extern "C" void kernel_launch(void* const* d_in, const int* in_sizes, int n_in,
                              void* d_out, int out_size)
{
    const float* x0 = (const float*)d_in[0];
    const void* ei = d_in[1];
    const float *Wl[5], *bl[5], *gl[5], *bel[5];
    for (int l = 0; l < 5; l++) {
        Wl[l]  = (const float*)d_in[2 + 4 * l];
        bl[l]  = (const float*)d_in[3 + 4 * l];
        gl[l]  = (const float*)d_in[4 + 4 * l];
        bel[l] = (const float*)d_in[5 + 4 * l];
    }
    const float* fcw = (const float*)d_in[22];
    const float* fcb = (const float*)d_in[23];
    float* out = (float*)d_out;
    const int n = NN, E = NE;
    (void)in_sizes; (void)n_in; (void)out_size;

    float *bufA, *bufB, *bufC, *di, *dis, *bn, *scale, *shift;
    int *src, *dst, *cnt, *rowptr, *woff;
    int2* csre;
    cudaGetSymbolAddress((void**)&bufA,  g_bufA);
    cudaGetSymbolAddress((void**)&bufB,  g_bufB);
    cudaGetSymbolAddress((void**)&bufC,  g_bufC);
    cudaGetSymbolAddress((void**)&src,   g_src);
    cudaGetSymbolAddress((void**)&dst,   g_dst);
    cudaGetSymbolAddress((void**)&cnt,   g_cnt);
    cudaGetSymbolAddress((void**)&rowptr,g_rowptr);
    cudaGetSymbolAddress((void**)&woff,  g_woff);
    cudaGetSymbolAddress((void**)&csre,  g_csre);
    cudaGetSymbolAddress((void**)&di,    g_di);
    cudaGetSymbolAddress((void**)&dis,   g_dis);
    cudaGetSymbolAddress((void**)&bn,    g_bn);
    cudaGetSymbolAddress((void**)&scale, g_scale);
    cudaGetSymbolAddress((void**)&shift, g_shift);

    int aggBlocks = (n + 7) / 8;
    int rowBlocks = (n + 127) / 128;
    float invN = 1.0f / (float)n;

    k_prep_edges<<<2048, 256>>>(ei, src, dst, cnt, E, n);
    k_scan_deg<<<1, 1024>>>(cnt, rowptr, woff, di, dis, n);
    k_csr<<<2048, 256>>>(src, dst, dis, woff, csre, E);

    // L0 (agg-first)
    k_agg<128, false, false><<<aggBlocks, 256>>>(x0, bufB, rowptr, csre, di, n,
                                                 nullptr, nullptr, nullptr, nullptr, nullptr);
    k_gemm<true, false><<<dim3(2, rowBlocks), 256>>>(bufB, Wl[0], bufC, n, 128, 128,
                                                     nullptr, nullptr, bl[0], bn, bn + 256);
    k_bn_finalize<<<1, 256>>>(gl[0], bel[0], 128, invN, bn, scale, shift);

    // L1 (agg-first)
    k_agg<128, false, true><<<aggBlocks, 256>>>(bufC, bufB, rowptr, csre, di, n,
                                                scale, shift, nullptr, nullptr, nullptr);
    k_gemm<true, false><<<dim3(4, rowBlocks), 256>>>(bufB, Wl[1], bufA, n, 128, 256,
                                                     nullptr, nullptr, bl[1], bn, bn + 256);
    k_bn_finalize<<<1, 256>>>(gl[1], bel[1], 256, invN, bn, scale, shift);

    // L2 (gemm-first)
    k_gemm<false, true><<<dim3(2, rowBlocks), 256>>>(bufA, Wl[2], bufB, n, 256, 128,
                                                     scale, shift, nullptr, nullptr, nullptr);
    k_agg<128, true, false><<<aggBlocks, 256>>>(bufB, bufC, rowptr, csre, di, n,
                                                nullptr, nullptr, bl[2], bn, bn + 256);
    k_bn_finalize<<<1, 256>>>(gl[2], bel[2], 128, invN, bn, scale, shift);

    // L3 (gemm-first)
    k_gemm<false, true><<<dim3(1, rowBlocks), 256>>>(bufC, Wl[3], bufB, n, 128, 64,
                                                     scale, shift, nullptr, nullptr, nullptr);
    k_agg<64, true, false><<<aggBlocks, 256>>>(bufB, bufA, rowptr, csre, di, n,
                                               nullptr, nullptr, bl[3], bn, bn + 256);
    k_bn_finalize<<<1, 256>>>(gl[3], bel[3], 64, invN, bn, scale, shift);

    // L4 (gemm-first)
    k_gemm<false, true><<<dim3(1, rowBlocks), 256>>>(bufA, Wl[4], bufB, n, 64, 32,
                                                     scale, shift, nullptr, nullptr, nullptr);
    k_agg<32, true, false><<<aggBlocks, 256>>>(bufB, bufC, rowptr, csre, di, n,
                                               nullptr, nullptr, bl[4], bn, bn + 256);
    k_bn_finalize<<<1, 256>>>(gl[4], bel[4], 32, invN, bn, scale, shift);

    // edge head
    int edgeBlocks = (E / 2 + 7) / 8;
    k_edge_out<<<edgeBlocks, 256>>>(bufC, src, dst, scale, shift, fcw, fcb, out, E);
}

// round 7
// speedup vs baseline: 1.3095x; 1.3095x over previous
#include <cuda_runtime.h>
#include <cuda_fp16.h>
#include <math.h>
#include <stdint.h>

#define NN 100000
#define NE 3200000
#define MAXD 256

typedef unsigned long long ull;

// ---------------- static device scratch (allocation-free contract) ----------------
__device__ float  g_bufA[(size_t)NN * MAXD];
__device__ float  g_bufB[(size_t)NN * MAXD];
__device__ float  g_bufC[(size_t)NN * MAXD];
__device__ __half g_bufH[(size_t)NN * 128];     // sequentially reused half tensor
__device__ int    g_src[NE];
__device__ int    g_dst[NE];
__device__ int    g_cnt[NN];       // invariant: zero at entry
__device__ int    g_rowptr[NN + 1];
__device__ int    g_woff[NN];
__device__ int2   g_csre[NE];      // packed {src, weight-bits}
__device__ float  g_di[NN];
__device__ float  g_dis[NN];
__device__ float  g_bn[512];       // invariant: zero at entry (finalize re-zeroes)
__device__ float  g_scale[256];
__device__ float  g_shift[256];

union H4 { __half h[4]; ull u; };

// ---------------- prep: detect dtype inline, convert, count in-degree ----------------
__global__ void k_prep_edges(const void* __restrict__ ei_raw,
                             int* __restrict__ src, int* __restrict__ dst,
                             int* __restrict__ cnt, int E, int n) {
    const unsigned int* w = (const unsigned int*)ei_raw;
    unsigned int probe = w[2 * (threadIdx.x & 255) + 1];
    int any = __syncthreads_or(probe != 0u);
    const int is64 = (any == 0);
    const long long* ei64 = (const long long*)ei_raw;
    const int* ei32 = (const int*)ei_raw;
    for (int e = blockIdx.x * blockDim.x + threadIdx.x; e < E; e += gridDim.x * blockDim.x) {
        int s, d;
        if (is64) { s = (int)ei64[e]; d = (int)ei64[(size_t)E + e]; }
        else      { s = ei32[e];      d = ei32[(size_t)E + e]; }
        if ((unsigned)s >= (unsigned)n) s = 0;
        if ((unsigned)d >= (unsigned)n) d = 0;
        src[e] = s;
        dst[e] = d;
        atomicAdd(&cnt[d], 1);
    }
}

// ---------------- single-block tiled coalesced scan + deg + cnt re-zero ----------------
__global__ void k_scan_deg(int* __restrict__ cnt, int* __restrict__ rowptr,
                           int* __restrict__ woff, float* __restrict__ di,
                           float* __restrict__ dis, int n) {
    __shared__ int wsum[32];
    __shared__ int s_off;
    int t = threadIdx.x, lane = t & 31, wid = t >> 5;
    if (t == 0) s_off = 0;
    __syncthreads();
    for (int base = 0; base < n; base += 1024) {
        int i = base + t;
        int c = (i < n) ? cnt[i] : 0;
        if (i < n) cnt[i] = 0;
        int x = c;
#pragma unroll
        for (int o = 1; o < 32; o <<= 1) {
            int v = __shfl_up_sync(0xffffffffu, x, o);
            if (lane >= o) x += v;
        }
        if (lane == 31) wsum[wid] = x;
        __syncthreads();
        if (wid == 0) {
            int y = wsum[lane];
#pragma unroll
            for (int o = 1; o < 32; o <<= 1) {
                int v = __shfl_up_sync(0xffffffffu, y, o);
                if (lane >= o) y += v;
            }
            wsum[lane] = y;
        }
        __syncthreads();
        int wbase = (wid == 0) ? 0 : wsum[wid - 1];
        int excl = x + wbase - c;
        int off0 = s_off;
        if (i < n) {
            int r = off0 + excl;
            rowptr[i] = r;
            woff[i]   = r;
            float dg = (float)c + 1.0f;
            di[i]  = 1.0f / dg;
            dis[i] = rsqrtf(dg);
        }
        __syncthreads();
        if (t == 1023) s_off = off0 + wsum[31];
        __syncthreads();
    }
    if (t == 0) rowptr[n] = s_off;
}

// ---------------- CSR scatter with packed (src, weight) ----------------
__global__ void k_csr(const int* __restrict__ src, const int* __restrict__ dst,
                      const float* __restrict__ dis, int* __restrict__ woff,
                      int2* __restrict__ csre, int E) {
    for (int e = blockIdx.x * blockDim.x + threadIdx.x; e < E; e += gridDim.x * blockDim.x) {
        int d = dst[e];
        int pos = atomicAdd(&woff[d], 1);
        int s = src[e];
        if (pos < E) {
            float w = dis[s] * dis[d];
            csre[pos] = make_int2(s, __float_as_int(w));
        }
    }
}

// ---------------- fp32 -> fp16 convert (x0 pre-pass) ----------------
__global__ void k_f2h(const float* __restrict__ x, __half* __restrict__ h, int total4) {
    for (int i = blockIdx.x * blockDim.x + threadIdx.x; i < total4; i += gridDim.x * blockDim.x) {
        float4 v = ((const float4*)x)[i];
        __half2* o = (__half2*)(h + 4 * (size_t)i);
        o[0] = __floats2half2_rn(v.x, v.y);
        o[1] = __floats2half2_rn(v.z, v.w);
    }
}

// ---------------- half-input aggregation: warp-per-node, half2 lanes ----------------
// out[i] = sum_e w_e * act(in[src_e]) + di[i]*act(in[i]) (+bias, +BN stats if EPI)
template <int D, bool EPI, bool AFF>
__global__ __launch_bounds__(256) void k_aggh(
    const __half* __restrict__ xin, float* __restrict__ xout,
    const int* __restrict__ rowptr, const int2* __restrict__ csre,
    const float* __restrict__ di, int n,
    const float* __restrict__ scale, const float* __restrict__ shift,
    const float* __restrict__ bias, float* __restrict__ bnsum, float* __restrict__ bnsq)
{
    constexpr int CPL2 = D / 64;   // half2 per lane
    int lane = threadIdx.x & 31;
    int node = blockIdx.x * 8 + (threadIdx.x >> 5);
    float2 acc[CPL2];
    float2 sc[CPL2], sh[CPL2];
#pragma unroll
    for (int j = 0; j < CPL2; j++) {
        acc[j] = make_float2(0.f, 0.f);
        if (AFF) {
            int f = 2 * lane + 64 * j;
            sc[j] = make_float2(scale[f], scale[f + 1]);
            sh[j] = make_float2(shift[f], shift[f + 1]);
        }
    }

    if (node < n) {
        int beg = rowptr[node], end = rowptr[node + 1];
        int e = beg;
        for (; e + 2 <= end; e += 2) {
            int2 p0 = __ldg(&csre[e]);
            int2 p1 = __ldg(&csre[e + 1]);
            float w0 = __int_as_float(p0.y);
            float w1 = __int_as_float(p1.y);
            const __half2* r0 = (const __half2*)(xin + (size_t)p0.x * D) + lane;
            const __half2* r1 = (const __half2*)(xin + (size_t)p1.x * D) + lane;
            __half2 h0[CPL2], h1[CPL2];
#pragma unroll
            for (int j = 0; j < CPL2; j++) h0[j] = __ldg(r0 + 32 * j);
#pragma unroll
            for (int j = 0; j < CPL2; j++) h1[j] = __ldg(r1 + 32 * j);
#pragma unroll
            for (int j = 0; j < CPL2; j++) {
                float2 v0 = __half22float2(h0[j]);
                float2 v1 = __half22float2(h1[j]);
                if (AFF) {
                    v0.x = fmaxf(v0.x * sc[j].x + sh[j].x, 0.f);
                    v0.y = fmaxf(v0.y * sc[j].y + sh[j].y, 0.f);
                    v1.x = fmaxf(v1.x * sc[j].x + sh[j].x, 0.f);
                    v1.y = fmaxf(v1.y * sc[j].y + sh[j].y, 0.f);
                }
                acc[j].x += w0 * v0.x + w1 * v1.x;
                acc[j].y += w0 * v0.y + w1 * v1.y;
            }
        }
        if (e < end) {
            int2 p0 = __ldg(&csre[e]);
            float w0 = __int_as_float(p0.y);
            const __half2* r0 = (const __half2*)(xin + (size_t)p0.x * D) + lane;
#pragma unroll
            for (int j = 0; j < CPL2; j++) {
                float2 v = __half22float2(__ldg(r0 + 32 * j));
                if (AFF) {
                    v.x = fmaxf(v.x * sc[j].x + sh[j].x, 0.f);
                    v.y = fmaxf(v.y * sc[j].y + sh[j].y, 0.f);
                }
                acc[j].x += w0 * v.x;
                acc[j].y += w0 * v.y;
            }
        }
        float dii = di[node];
        const __half2* r = (const __half2*)(xin + (size_t)node * D) + lane;
#pragma unroll
        for (int j = 0; j < CPL2; j++) {
            float2 v = __half22float2(__ldg(r + 32 * j));
            if (AFF) {
                v.x = fmaxf(v.x * sc[j].x + sh[j].x, 0.f);
                v.y = fmaxf(v.y * sc[j].y + sh[j].y, 0.f);
            }
            acc[j].x += dii * v.x;
            acc[j].y += dii * v.y;
            int f = 2 * lane + 64 * j;
            if (EPI) { acc[j].x += bias[f]; acc[j].y += bias[f + 1]; }
            *(float2*)(xout + (size_t)node * D + f) = acc[j];
        }
    }
    if constexpr (EPI) {
        __shared__ float csum[D];
        __shared__ float csq[D];
        for (int t = threadIdx.x; t < D; t += blockDim.x) { csum[t] = 0.f; csq[t] = 0.f; }
        __syncthreads();
        if (node < n) {
#pragma unroll
            for (int j = 0; j < CPL2; j++) {
                int f = 2 * lane + 64 * j;
                atomicAdd(&csum[f], acc[j].x);
                atomicAdd(&csum[f + 1], acc[j].y);
                atomicAdd(&csq[f], acc[j].x * acc[j].x);
                atomicAdd(&csq[f + 1], acc[j].y * acc[j].y);
            }
        }
        __syncthreads();
        for (int t = threadIdx.x; t < D; t += blockDim.x) {
            atomicAdd(&bnsum[t], csum[t]);
            atomicAdd(&bnsq[t], csq[t]);
        }
    }
}

// ---------------- fp32-input aggregation (L4 only, D=32): out = half ----------------
__global__ __launch_bounds__(256) void k_agg32(
    const float* __restrict__ xin, __half* __restrict__ xout,
    const int* __restrict__ rowptr, const int2* __restrict__ csre,
    const float* __restrict__ di, int n,
    const float* __restrict__ bias, float* __restrict__ bnsum, float* __restrict__ bnsq)
{
    int lane = threadIdx.x & 31;
    int node = blockIdx.x * 8 + (threadIdx.x >> 5);
    float acc = 0.f;

    if (node < n) {
        int beg = rowptr[node], end = rowptr[node + 1];
        int e = beg;
        for (; e + 2 <= end; e += 2) {
            int2 p0 = __ldg(&csre[e]);
            int2 p1 = __ldg(&csre[e + 1]);
            float v0 = __ldg(xin + (size_t)p0.x * 32 + lane);
            float v1 = __ldg(xin + (size_t)p1.x * 32 + lane);
            acc += __int_as_float(p0.y) * v0;
            acc += __int_as_float(p1.y) * v1;
        }
        if (e < end) {
            int2 p0 = __ldg(&csre[e]);
            acc += __int_as_float(p0.y) * __ldg(xin + (size_t)p0.x * 32 + lane);
        }
        acc += di[node] * __ldg(xin + (size_t)node * 32 + lane);
        acc += bias[lane];
        xout[(size_t)node * 32 + lane] = __float2half_rn(acc);
    }
    __shared__ float csum[32];
    __shared__ float csq[32];
    if (threadIdx.x < 32) { csum[threadIdx.x] = 0.f; csq[threadIdx.x] = 0.f; }
    __syncthreads();
    if (node < n) {
        atomicAdd(&csum[lane], acc);
        atomicAdd(&csq[lane], acc * acc);
    }
    __syncthreads();
    if (threadIdx.x < 32) {
        atomicAdd(&bnsum[threadIdx.x], csum[threadIdx.x]);
        atomicAdd(&bnsq[threadIdx.x], csq[threadIdx.x]);
    }
}

// ---------------- R3-proven fp32 GEMM, 128x64 tile, 8x4 micro; optional half output ----------------
template <bool EPI, bool AFF, bool OUTH>
__global__ __launch_bounds__(256) void k_gemm(
    const float* __restrict__ A, const float* __restrict__ W, void* __restrict__ Cout,
    int M, int K, int Nc,
    const float* __restrict__ scale, const float* __restrict__ shift,
    const float* __restrict__ bias, float* __restrict__ bnsum, float* __restrict__ bnsq)
{
    __shared__ float As[16][128];
    __shared__ float Bs[16][64];
    int tid = threadIdx.x;
    int tx = tid & 15;
    int ty = tid >> 4;
    int row0 = blockIdx.y * 128;
    int col0 = blockIdx.x * 64;

    float acc[8][4];
#pragma unroll
    for (int i = 0; i < 8; i++)
#pragma unroll
        for (int j = 0; j < 4; j++) acc[i][j] = 0.f;

    int arow = tid >> 2;
    int afc  = tid & 3;
    int bkr  = tid >> 4;
    int bfc  = tid & 15;

    for (int k0 = 0; k0 < K; k0 += 16) {
#pragma unroll
        for (int t = 0; t < 2; t++) {
            int m = arow + 64 * t;
            int gm = row0 + m;
            float4 v = make_float4(0.f, 0.f, 0.f, 0.f);
            if (gm < M) v = *(const float4*)(A + (size_t)gm * K + k0 + 4 * afc);
            if (AFF) {
                int kk4 = k0 + 4 * afc;
                float4 s4 = *(const float4*)(scale + kk4);
                float4 h4 = *(const float4*)(shift + kk4);
                v.x = fmaxf(v.x * s4.x + h4.x, 0.f);
                v.y = fmaxf(v.y * s4.y + h4.y, 0.f);
                v.z = fmaxf(v.z * s4.z + h4.z, 0.f);
                v.w = fmaxf(v.w * s4.w + h4.w, 0.f);
            }
            As[4 * afc + 0][m] = v.x;
            As[4 * afc + 1][m] = v.y;
            As[4 * afc + 2][m] = v.z;
            As[4 * afc + 3][m] = v.w;
        }
        {
            float4 v = make_float4(0.f, 0.f, 0.f, 0.f);
            int gc = col0 + 4 * bfc;
            if (gc < Nc) v = *(const float4*)(W + (size_t)(k0 + bkr) * Nc + gc);
            *(float4*)&Bs[bkr][4 * bfc] = v;
        }
        __syncthreads();
#pragma unroll
        for (int kk = 0; kk < 16; kk++) {
            float4 a0 = *(const float4*)&As[kk][ty * 8];
            float4 a1 = *(const float4*)&As[kk][ty * 8 + 4];
            float4 b  = *(const float4*)&Bs[kk][tx * 4];
            float ra[8] = {a0.x, a0.y, a0.z, a0.w, a1.x, a1.y, a1.z, a1.w};
            float rb[4] = {b.x, b.y, b.z, b.w};
#pragma unroll
            for (int i = 0; i < 8; i++)
#pragma unroll
                for (int j = 0; j < 4; j++) acc[i][j] += ra[i] * rb[j];
        }
        __syncthreads();
    }

    int colbase = col0 + tx * 4;
    bool colok = colbase < Nc;

    if constexpr (!EPI) {
#pragma unroll
        for (int i = 0; i < 8; i++) {
            int row = row0 + ty * 8 + i;
            if (row < M && colok) {
                if (OUTH) {
                    H4 x;
                    x.h[0] = __float2half_rn(acc[i][0]);
                    x.h[1] = __float2half_rn(acc[i][1]);
                    x.h[2] = __float2half_rn(acc[i][2]);
                    x.h[3] = __float2half_rn(acc[i][3]);
                    *(ull*)((__half*)Cout + (size_t)row * Nc + colbase) = x.u;
                } else {
                    *(float4*)((float*)Cout + (size_t)row * Nc + colbase) =
                        make_float4(acc[i][0], acc[i][1], acc[i][2], acc[i][3]);
                }
            }
        }
    } else {
        __shared__ float csum[64];
        __shared__ float csq[64];
        if (tid < 64) { csum[tid] = 0.f; csq[tid] = 0.f; }
        __syncthreads();
        float4 b4 = colok ? *(const float4*)(bias + colbase) : make_float4(0.f, 0.f, 0.f, 0.f);
        float tsum[4] = {0.f, 0.f, 0.f, 0.f};
        float tsq[4]  = {0.f, 0.f, 0.f, 0.f};
#pragma unroll
        for (int i = 0; i < 8; i++) {
            int row = row0 + ty * 8 + i;
            if (row < M && colok) {
                float v0 = acc[i][0] + b4.x;
                float v1 = acc[i][1] + b4.y;
                float v2 = acc[i][2] + b4.z;
                float v3 = acc[i][3] + b4.w;
                if (OUTH) {
                    H4 x;
                    x.h[0] = __float2half_rn(v0);
                    x.h[1] = __float2half_rn(v1);
                    x.h[2] = __float2half_rn(v2);
                    x.h[3] = __float2half_rn(v3);
                    *(ull*)((__half*)Cout + (size_t)row * Nc + colbase) = x.u;
                } else {
                    *(float4*)((float*)Cout + (size_t)row * Nc + colbase) =
                        make_float4(v0, v1, v2, v3);
                }
                tsum[0] += v0; tsum[1] += v1; tsum[2] += v2; tsum[3] += v3;
                tsq[0] += v0 * v0; tsq[1] += v1 * v1; tsq[2] += v2 * v2; tsq[3] += v3 * v3;
            }
        }
#pragma unroll
        for (int j = 0; j < 4; j++) {
            atomicAdd(&csum[tx * 4 + j], tsum[j]);
            atomicAdd(&csq[tx * 4 + j], tsq[j]);
        }
        __syncthreads();
        if (tid < 64 && col0 + tid < Nc) {
            atomicAdd(&bnsum[col0 + tid], csum[tid]);
            atomicAdd(&bnsq[col0 + tid], csq[tid]);
        }
    }
}

// ---------------- BN finalize: scale/shift from stats, then re-zero stats ----------------
__global__ void k_bn_finalize(const float* __restrict__ g, const float* __restrict__ be,
                              int d, float invN, float* __restrict__ bn,
                              float* __restrict__ scale, float* __restrict__ shift) {
    int t = threadIdx.x;
    float s = bn[t], q = bn[256 + t];
    if (t < d) {
        float mu  = s * invN;
        float var = q * invN - mu * mu;
        float rstd = rsqrtf(fmaxf(var, 0.f) + 1e-5f);
        float sc = g[t] * rstd;
        scale[t] = sc;
        shift[t] = be[t] - mu * sc;
    }
    bn[t] = 0.f;
    bn[256 + t] = 0.f;
}

// ---------------- edge head: 2 edges per warp, half input, fused affine+relu ----------------
__global__ __launch_bounds__(256) void k_edge_out(
    const __half* __restrict__ conv, const int* __restrict__ src, const int* __restrict__ dst,
    const float* __restrict__ scale, const float* __restrict__ shift,
    const float* __restrict__ fcw, const float* __restrict__ fcb,
    float* __restrict__ out, int E)
{
    int warp = (blockIdx.x * blockDim.x + threadIdx.x) >> 5;
    int lane = threadIdx.x & 31;
    int half = lane >> 4;
    int l16  = lane & 15;
    int eid = warp * 2 + half;
    if (eid >= E) return;
    int s = src[eid], d = dst[eid];
    const __half2* rs = (const __half2*)(conv + (size_t)s * 32);
    const __half2* rd = (const __half2*)(conv + (size_t)d * 32);
    int f = 2 * l16;
    float2 a = __half22float2(__ldg(rs + l16));
    float2 b = __half22float2(__ldg(rd + l16));
    float scx = scale[f], scy = scale[f + 1];
    float shx = shift[f], shy = shift[f + 1];
    a.x = fmaxf(a.x * scx + shx, 0.f);
    a.y = fmaxf(a.y * scy + shy, 0.f);
    b.x = fmaxf(b.x * scx + shx, 0.f);
    b.y = fmaxf(b.y * scy + shy, 0.f);
    float v = a.x * b.x * fcw[f] + a.y * b.y * fcw[f + 1];
#pragma unroll
    for (int o = 8; o; o >>= 1) v += __shfl_xor_sync(0xffffffffu, v, o);
    if (l16 == 0) out[eid] = 1.f / (1.f + expf(-(v + fcb[0])));
}

// ---------------- host ----------------
extern "C" void kernel_launch(void* const* d_in, const int* in_sizes, int n_in,
                              void* d_out, int out_size)
{
    const float* x0 = (const float*)d_in[0];
    const void* ei = d_in[1];
    const float *Wl[5], *bl[5], *gl[5], *bel[5];
    for (int l = 0; l < 5; l++) {
        Wl[l]  = (const float*)d_in[2 + 4 * l];
        bl[l]  = (const float*)d_in[3 + 4 * l];
        gl[l]  = (const float*)d_in[4 + 4 * l];
        bel[l] = (const float*)d_in[5 + 4 * l];
    }
    const float* fcw = (const float*)d_in[22];
    const float* fcb = (const float*)d_in[23];
    float* out = (float*)d_out;
    const int n = NN, E = NE;
    (void)in_sizes; (void)n_in; (void)out_size;

    float *bufA, *bufB, *bufC, *di, *dis, *bn, *scale, *shift;
    __half* bufH;
    int *src, *dst, *cnt, *rowptr, *woff;
    int2* csre;
    cudaGetSymbolAddress((void**)&bufA,  g_bufA);
    cudaGetSymbolAddress((void**)&bufB,  g_bufB);
    cudaGetSymbolAddress((void**)&bufC,  g_bufC);
    cudaGetSymbolAddress((void**)&bufH,  g_bufH);
    cudaGetSymbolAddress((void**)&src,   g_src);
    cudaGetSymbolAddress((void**)&dst,   g_dst);
    cudaGetSymbolAddress((void**)&cnt,   g_cnt);
    cudaGetSymbolAddress((void**)&rowptr,g_rowptr);
    cudaGetSymbolAddress((void**)&woff,  g_woff);
    cudaGetSymbolAddress((void**)&csre,  g_csre);
    cudaGetSymbolAddress((void**)&di,    g_di);
    cudaGetSymbolAddress((void**)&dis,   g_dis);
    cudaGetSymbolAddress((void**)&bn,    g_bn);
    cudaGetSymbolAddress((void**)&scale, g_scale);
    cudaGetSymbolAddress((void**)&shift, g_shift);

    int aggBlocks = (n + 7) / 8;
    int rowBlocks = (n + 127) / 128;
    float invN = 1.0f / (float)n;

    k_prep_edges<<<2048, 256>>>(ei, src, dst, cnt, E, n);
    k_scan_deg<<<1, 1024>>>(cnt, rowptr, woff, di, dis, n);
    k_csr<<<2048, 256>>>(src, dst, dis, woff, csre, E);

    // x0 -> half
    k_f2h<<<1024, 256>>>(x0, bufH, n * 128 / 4);

    // L0 (agg-first): aggh(x0h)->B ; GEMM B@W0+b0 -> conv0h (half, stats) ; finalize
    k_aggh<128, false, false><<<aggBlocks, 256>>>(bufH, bufB, rowptr, csre, di, n,
                                                  nullptr, nullptr, nullptr, nullptr, nullptr);
    k_gemm<true, false, true><<<dim3(2, rowBlocks), 256>>>(bufB, Wl[0], bufH, n, 128, 128,
                                                           nullptr, nullptr, bl[0], bn, bn + 256);
    k_bn_finalize<<<1, 256>>>(gl[0], bel[0], 128, invN, bn, scale, shift);

    // L1 (agg-first): aggh(act(conv0h))->B ; GEMM B@W1+b1 -> conv1 fp32 (stats) ; finalize
    k_aggh<128, false, true><<<aggBlocks, 256>>>(bufH, bufB, rowptr, csre, di, n,
                                                 scale, shift, nullptr, nullptr, nullptr);
    k_gemm<true, false, false><<<dim3(4, rowBlocks), 256>>>(bufB, Wl[1], bufA, n, 128, 256,
                                                            nullptr, nullptr, bl[1], bn, bn + 256);
    k_bn_finalize<<<1, 256>>>(gl[1], bel[1], 256, invN, bn, scale, shift);

    // L2 (gemm-first): GEMM act(conv1)@W2 -> h2 half ; aggh h2 + b2 -> conv2 fp32 (stats)
    k_gemm<false, true, true><<<dim3(2, rowBlocks), 256>>>(bufA, Wl[2], bufH, n, 256, 128,
                                                           scale, shift, nullptr, nullptr, nullptr);
    k_aggh<128, true, false><<<aggBlocks, 256>>>(bufH, bufC, rowptr, csre, di, n,
                                                 nullptr, nullptr, bl[2], bn, bn + 256);
    k_bn_finalize<<<1, 256>>>(gl[2], bel[2], 128, invN, bn, scale, shift);

    // L3: GEMM act(conv2)@W3 -> h3 half ; aggh h3 + b3 -> conv3 fp32 (stats)
    k_gemm<false, true, true><<<dim3(1, rowBlocks), 256>>>(bufC, Wl[3], bufH, n, 128, 64,
                                                           scale, shift, nullptr, nullptr, nullptr);
    k_aggh<64, true, false><<<aggBlocks, 256>>>(bufH, bufA, rowptr, csre, di, n,
                                                nullptr, nullptr, bl[3], bn, bn + 256);
    k_bn_finalize<<<1, 256>>>(gl[3], bel[3], 64, invN, bn, scale, shift);

    // L4: GEMM act(conv3)@W4 -> h4 fp32 ; agg32 h4 + b4 -> conv4 half (stats)
    k_gemm<false, true, false><<<dim3(1, rowBlocks), 256>>>(bufA, Wl[4], bufB, n, 64, 32,
                                                            scale, shift, nullptr, nullptr, nullptr);
    k_agg32<<<aggBlocks, 256>>>(bufB, bufH, rowptr, csre, di, n, bl[4], bn, bn + 256);
    k_bn_finalize<<<1, 256>>>(gl[4], bel[4], 32, invN, bn, scale, shift);

    // edge head
    int edgeBlocks = (E / 2 + 7) / 8;
    k_edge_out<<<edgeBlocks, 256>>>(bufH, src, dst, scale, shift, fcw, fcb, out, E);
}

// round 8
// speedup vs baseline: 1.4573x; 1.1129x over previous
#include <cuda_runtime.h>
#include <cuda_fp16.h>
#include <math.h>
#include <stdint.h>

#define NN 100000
#define NE 3200000
#define MAXD 256

typedef unsigned long long ull;

// ---------------- static device scratch (allocation-free contract) ----------------
__device__ float  g_bufA[(size_t)NN * MAXD];
__device__ float  g_bufB[(size_t)NN * MAXD];
__device__ float  g_bufC[(size_t)NN * MAXD];
__device__ __half g_bufH[(size_t)NN * 128];
__device__ int    g_src[NE];
__device__ int    g_dst[NE];
__device__ int    g_cnt[NN];       // invariant: zero at entry
__device__ int    g_rowptr[NN + 1];
__device__ int    g_woff[NN];
__device__ int2   g_csre[NE];      // packed {src, weight-bits}
__device__ float  g_di[NN];
__device__ float  g_dis[NN];
__device__ float  g_bn[512];       // invariant: zero at entry (finalize re-zeroes)
__device__ float  g_scale[256];
__device__ float  g_shift[256];

__device__ __forceinline__ unsigned pack_h2(float a, float b) {
    __half2 h = __floats2half2_rn(a, b);
    return *reinterpret_cast<unsigned*>(&h);
}
__device__ __forceinline__ float2 unpack_h2(unsigned u) {
    __half2 h = *reinterpret_cast<__half2*>(&u);
    return __half22float2(h);
}

#define MMA_F16(c, a, b)                                                               \
    asm volatile(                                                                      \
        "mma.sync.aligned.m16n8k16.row.col.f32.f16.f16.f32 "                           \
        "{%0,%1,%2,%3},{%4,%5,%6,%7},{%8,%9},{%0,%1,%2,%3};"                           \
        : "+f"((c)[0]), "+f"((c)[1]), "+f"((c)[2]), "+f"((c)[3])                       \
        : "r"((a)[0]), "r"((a)[1]), "r"((a)[2]), "r"((a)[3]), "r"((b)[0]), "r"((b)[1]))

// ---------------- prep: detect dtype inline, convert, count in-degree ----------------
__global__ void k_prep_edges(const void* __restrict__ ei_raw,
                             int* __restrict__ src, int* __restrict__ dst,
                             int* __restrict__ cnt, int E, int n) {
    const unsigned int* w = (const unsigned int*)ei_raw;
    unsigned int probe = w[2 * (threadIdx.x & 255) + 1];
    int any = __syncthreads_or(probe != 0u);
    const int is64 = (any == 0);
    const long long* ei64 = (const long long*)ei_raw;
    const int* ei32 = (const int*)ei_raw;
    for (int e = blockIdx.x * blockDim.x + threadIdx.x; e < E; e += gridDim.x * blockDim.x) {
        int s, d;
        if (is64) { s = (int)ei64[e]; d = (int)ei64[(size_t)E + e]; }
        else      { s = ei32[e];      d = ei32[(size_t)E + e]; }
        if ((unsigned)s >= (unsigned)n) s = 0;
        if ((unsigned)d >= (unsigned)n) d = 0;
        src[e] = s;
        dst[e] = d;
        atomicAdd(&cnt[d], 1);
    }
}

// ---------------- single-block tiled coalesced scan + deg + cnt re-zero ----------------
__global__ void k_scan_deg(int* __restrict__ cnt, int* __restrict__ rowptr,
                           int* __restrict__ woff, float* __restrict__ di,
                           float* __restrict__ dis, int n) {
    __shared__ int wsum[32];
    __shared__ int s_off;
    int t = threadIdx.x, lane = t & 31, wid = t >> 5;
    if (t == 0) s_off = 0;
    __syncthreads();
    for (int base = 0; base < n; base += 1024) {
        int i = base + t;
        int c = (i < n) ? cnt[i] : 0;
        if (i < n) cnt[i] = 0;
        int x = c;
#pragma unroll
        for (int o = 1; o < 32; o <<= 1) {
            int v = __shfl_up_sync(0xffffffffu, x, o);
            if (lane >= o) x += v;
        }
        if (lane == 31) wsum[wid] = x;
        __syncthreads();
        if (wid == 0) {
            int y = wsum[lane];
#pragma unroll
            for (int o = 1; o < 32; o <<= 1) {
                int v = __shfl_up_sync(0xffffffffu, y, o);
                if (lane >= o) y += v;
            }
            wsum[lane] = y;
        }
        __syncthreads();
        int wbase = (wid == 0) ? 0 : wsum[wid - 1];
        int excl = x + wbase - c;
        int off0 = s_off;
        if (i < n) {
            int r = off0 + excl;
            rowptr[i] = r;
            woff[i]   = r;
            float dg = (float)c + 1.0f;
            di[i]  = 1.0f / dg;
            dis[i] = rsqrtf(dg);
        }
        __syncthreads();
        if (t == 1023) s_off = off0 + wsum[31];
        __syncthreads();
    }
    if (t == 0) rowptr[n] = s_off;
}

// ---------------- CSR scatter with packed (src, weight) ----------------
__global__ void k_csr(const int* __restrict__ src, const int* __restrict__ dst,
                      const float* __restrict__ dis, int* __restrict__ woff,
                      int2* __restrict__ csre, int E) {
    for (int e = blockIdx.x * blockDim.x + threadIdx.x; e < E; e += gridDim.x * blockDim.x) {
        int d = dst[e];
        int pos = atomicAdd(&woff[d], 1);
        int s = src[e];
        if (pos < E) {
            float w = dis[s] * dis[d];
            csre[pos] = make_int2(s, __float_as_int(w));
        }
    }
}

// ---------------- fp32 -> fp16 convert (x0 pre-pass) ----------------
__global__ void k_f2h(const float* __restrict__ x, __half* __restrict__ h, int total4) {
    for (int i = blockIdx.x * blockDim.x + threadIdx.x; i < total4; i += gridDim.x * blockDim.x) {
        float4 v = ((const float4*)x)[i];
        __half2* o = (__half2*)(h + 4 * (size_t)i);
        o[0] = __floats2half2_rn(v.x, v.y);
        o[1] = __floats2half2_rn(v.z, v.w);
    }
}

// ---------------- half aggregation: warp-per-node, half2 lanes, half output ----------------
template <int D, bool EPI, bool AFF>
__global__ __launch_bounds__(256) void k_aggh(
    const __half* __restrict__ xin, __half* __restrict__ xout,
    const int* __restrict__ rowptr, const int2* __restrict__ csre,
    const float* __restrict__ di, int n,
    const float* __restrict__ scale, const float* __restrict__ shift,
    const float* __restrict__ bias, float* __restrict__ bnsum, float* __restrict__ bnsq)
{
    constexpr int CPL2 = D / 64;
    int lane = threadIdx.x & 31;
    int node = blockIdx.x * 8 + (threadIdx.x >> 5);
    float2 acc[CPL2];
    float2 sc[CPL2], sh[CPL2];
#pragma unroll
    for (int j = 0; j < CPL2; j++) {
        acc[j] = make_float2(0.f, 0.f);
        if (AFF) {
            int f = 2 * lane + 64 * j;
            sc[j] = make_float2(scale[f], scale[f + 1]);
            sh[j] = make_float2(shift[f], shift[f + 1]);
        }
    }

    if (node < n) {
        int beg = rowptr[node], end = rowptr[node + 1];
        int e = beg;
        for (; e + 2 <= end; e += 2) {
            int2 p0 = __ldg(&csre[e]);
            int2 p1 = __ldg(&csre[e + 1]);
            float w0 = __int_as_float(p0.y);
            float w1 = __int_as_float(p1.y);
            const __half2* r0 = (const __half2*)(xin + (size_t)p0.x * D) + lane;
            const __half2* r1 = (const __half2*)(xin + (size_t)p1.x * D) + lane;
            __half2 h0[CPL2], h1[CPL2];
#pragma unroll
            for (int j = 0; j < CPL2; j++) h0[j] = __ldg(r0 + 32 * j);
#pragma unroll
            for (int j = 0; j < CPL2; j++) h1[j] = __ldg(r1 + 32 * j);
#pragma unroll
            for (int j = 0; j < CPL2; j++) {
                float2 v0 = __half22float2(h0[j]);
                float2 v1 = __half22float2(h1[j]);
                if (AFF) {
                    v0.x = fmaxf(v0.x * sc[j].x + sh[j].x, 0.f);
                    v0.y = fmaxf(v0.y * sc[j].y + sh[j].y, 0.f);
                    v1.x = fmaxf(v1.x * sc[j].x + sh[j].x, 0.f);
                    v1.y = fmaxf(v1.y * sc[j].y + sh[j].y, 0.f);
                }
                acc[j].x += w0 * v0.x + w1 * v1.x;
                acc[j].y += w0 * v0.y + w1 * v1.y;
            }
        }
        if (e < end) {
            int2 p0 = __ldg(&csre[e]);
            float w0 = __int_as_float(p0.y);
            const __half2* r0 = (const __half2*)(xin + (size_t)p0.x * D) + lane;
#pragma unroll
            for (int j = 0; j < CPL2; j++) {
                float2 v = __half22float2(__ldg(r0 + 32 * j));
                if (AFF) {
                    v.x = fmaxf(v.x * sc[j].x + sh[j].x, 0.f);
                    v.y = fmaxf(v.y * sc[j].y + sh[j].y, 0.f);
                }
                acc[j].x += w0 * v.x;
                acc[j].y += w0 * v.y;
            }
        }
        float dii = di[node];
        const __half2* r = (const __half2*)(xin + (size_t)node * D) + lane;
        __half2* orow = (__half2*)(xout + (size_t)node * D);
#pragma unroll
        for (int j = 0; j < CPL2; j++) {
            float2 v = __half22float2(__ldg(r + 32 * j));
            if (AFF) {
                v.x = fmaxf(v.x * sc[j].x + sh[j].x, 0.f);
                v.y = fmaxf(v.y * sc[j].y + sh[j].y, 0.f);
            }
            acc[j].x += dii * v.x;
            acc[j].y += dii * v.y;
            if (EPI) {
                int f = 2 * lane + 64 * j;
                acc[j].x += bias[f];
                acc[j].y += bias[f + 1];
            }
            orow[lane + 32 * j] = __floats2half2_rn(acc[j].x, acc[j].y);
        }
    }
    if constexpr (EPI) {
        __shared__ float csum[D];
        __shared__ float csq[D];
        for (int t = threadIdx.x; t < D; t += blockDim.x) { csum[t] = 0.f; csq[t] = 0.f; }
        __syncthreads();
        if (node < n) {
#pragma unroll
            for (int j = 0; j < CPL2; j++) {
                int f = 2 * lane + 64 * j;
                atomicAdd(&csum[f], acc[j].x);
                atomicAdd(&csum[f + 1], acc[j].y);
                atomicAdd(&csq[f], acc[j].x * acc[j].x);
                atomicAdd(&csq[f + 1], acc[j].y * acc[j].y);
            }
        }
        __syncthreads();
        for (int t = threadIdx.x; t < D; t += blockDim.x) {
            atomicAdd(&bnsum[t], csum[t]);
            atomicAdd(&bnsq[t], csq[t]);
        }
    }
}

// ---------------- fp32-input aggregation (L4, D=32) -> half out + stats ----------------
__global__ __launch_bounds__(256) void k_agg32(
    const float* __restrict__ xin, __half* __restrict__ xout,
    const int* __restrict__ rowptr, const int2* __restrict__ csre,
    const float* __restrict__ di, int n,
    const float* __restrict__ bias, float* __restrict__ bnsum, float* __restrict__ bnsq)
{
    int lane = threadIdx.x & 31;
    int node = blockIdx.x * 8 + (threadIdx.x >> 5);
    float acc = 0.f;

    if (node < n) {
        int beg = rowptr[node], end = rowptr[node + 1];
        int e = beg;
        for (; e + 2 <= end; e += 2) {
            int2 p0 = __ldg(&csre[e]);
            int2 p1 = __ldg(&csre[e + 1]);
            float v0 = __ldg(xin + (size_t)p0.x * 32 + lane);
            float v1 = __ldg(xin + (size_t)p1.x * 32 + lane);
            acc += __int_as_float(p0.y) * v0;
            acc += __int_as_float(p1.y) * v1;
        }
        if (e < end) {
            int2 p0 = __ldg(&csre[e]);
            acc += __int_as_float(p0.y) * __ldg(xin + (size_t)p0.x * 32 + lane);
        }
        acc += di[node] * __ldg(xin + (size_t)node * 32 + lane);
        acc += bias[lane];
        xout[(size_t)node * 32 + lane] = __float2half_rn(acc);
    }
    __shared__ float csum[32];
    __shared__ float csq[32];
    if (threadIdx.x < 32) { csum[threadIdx.x] = 0.f; csq[threadIdx.x] = 0.f; }
    __syncthreads();
    if (node < n) {
        atomicAdd(&csum[lane], acc);
        atomicAdd(&csq[lane], acc * acc);
    }
    __syncthreads();
    if (threadIdx.x < 32) {
        atomicAdd(&bnsum[threadIdx.x], csum[threadIdx.x]);
        atomicAdd(&bnsq[threadIdx.x], csq[threadIdx.x]);
    }
}

// ---------------- fp16 tensor-core GEMM (single MMA pass, fp32 accum) ----------------
// C[M,Nc] = act(A_h)[M,K] @ half(W)[K,Nc] (+bias); optional half out; optional BN stats.
template <bool EPI, bool AFF, bool OUTH>
__global__ __launch_bounds__(256) void k_gemm16(
    const __half* __restrict__ A, const float* __restrict__ W, void* __restrict__ Cout,
    int M, int K, int Nc,
    const float* __restrict__ scale, const float* __restrict__ shift,
    const float* __restrict__ bias, float* __restrict__ bnsum, float* __restrict__ bnsq)
{
    __shared__ unsigned As[128][8];   // [m][k-pair] fp16 pairs
    __shared__ unsigned Bs[64][8];    // [n][k-pair]
    int tid = threadIdx.x;
    int row0 = blockIdx.y * 128, col0 = blockIdx.x * 64;
    int w = tid >> 5, lane = tid & 31;
    int wm = w & 3, wn = w >> 2;          // 4x2 warp grid, warp tile 32x32
    int g = lane >> 2, t = lane & 3;

    float acc[2][4][4];
#pragma unroll
    for (int mi = 0; mi < 2; mi++)
#pragma unroll
        for (int ni = 0; ni < 4; ni++)
#pragma unroll
            for (int q = 0; q < 4; q++) acc[mi][ni][q] = 0.f;

    int am_ld = tid >> 1;                 // 0..127
    int ah_ld = (tid & 1);                // half of the 16-k chunk (8 halves)
    int bn_ld = tid >> 2;                 // 0..63
    int bk_ld = (tid & 3) * 4;            // k offset (4 halves)

    for (int k0 = 0; k0 < K; k0 += 16) {
        // --- stage A: 128 rows x 16 halves ---
        {
            int gm = row0 + am_ld;
            uint4 v = make_uint4(0u, 0u, 0u, 0u);
            if (gm < M) v = *(const uint4*)(A + (size_t)gm * K + k0 + 8 * ah_ld);
            if (AFF) {
                int kk = k0 + 8 * ah_ld;
                unsigned* pv = &v.x;
#pragma unroll
                for (int i = 0; i < 4; i++) {
                    float2 f = unpack_h2(pv[i]);
                    int c = kk + 2 * i;
                    f.x = fmaxf(f.x * scale[c] + shift[c], 0.f);
                    f.y = fmaxf(f.y * scale[c + 1] + shift[c + 1], 0.f);
                    pv[i] = pack_h2(f.x, f.y);
                }
            }
            As[am_ld][4 * ah_ld + 0] = v.x;
            As[am_ld][4 * ah_ld + 1] = v.y;
            As[am_ld][4 * ah_ld + 2] = v.z;
            As[am_ld][4 * ah_ld + 3] = v.w;
        }
        // --- stage B: W[k][n] -> fp16 [n][k] ---
        {
            int gc = col0 + bn_ld;
            float w0 = 0.f, w1 = 0.f, w2 = 0.f, w3 = 0.f;
            if (gc < Nc) {
                w0 = W[(size_t)(k0 + bk_ld + 0) * Nc + gc];
                w1 = W[(size_t)(k0 + bk_ld + 1) * Nc + gc];
                w2 = W[(size_t)(k0 + bk_ld + 2) * Nc + gc];
                w3 = W[(size_t)(k0 + bk_ld + 3) * Nc + gc];
            }
            Bs[bn_ld][bk_ld / 2 + 0] = pack_h2(w0, w1);
            Bs[bn_ld][bk_ld / 2 + 1] = pack_h2(w2, w3);
        }
        __syncthreads();
        // --- fragments + single MMA each ---
        unsigned a[2][4], b[4][2];
#pragma unroll
        for (int mi = 0; mi < 2; mi++) {
            int r = wm * 32 + mi * 16;
            a[mi][0] = As[r + g][t];
            a[mi][1] = As[r + g + 8][t];
            a[mi][2] = As[r + g][t + 4];
            a[mi][3] = As[r + g + 8][t + 4];
        }
#pragma unroll
        for (int ni = 0; ni < 4; ni++) {
            int c = wn * 32 + ni * 8;
            b[ni][0] = Bs[c + g][t];
            b[ni][1] = Bs[c + g][t + 4];
        }
#pragma unroll
        for (int mi = 0; mi < 2; mi++)
#pragma unroll
            for (int ni = 0; ni < 4; ni++)
                MMA_F16(acc[mi][ni], a[mi], b[ni]);
        __syncthreads();
    }

    // --- epilogue ---
    if constexpr (!EPI) {
#pragma unroll
        for (int mi = 0; mi < 2; mi++) {
            int rt = row0 + wm * 32 + mi * 16 + g;
#pragma unroll
            for (int ni = 0; ni < 4; ni++) {
                int gc = col0 + wn * 32 + ni * 8 + 2 * t;
                if (gc < Nc) {
                    if (rt < M) {
                        if (OUTH)
                            *(unsigned*)((__half*)Cout + (size_t)rt * Nc + gc) =
                                pack_h2(acc[mi][ni][0], acc[mi][ni][1]);
                        else
                            *(float2*)((float*)Cout + (size_t)rt * Nc + gc) =
                                make_float2(acc[mi][ni][0], acc[mi][ni][1]);
                    }
                    if (rt + 8 < M) {
                        if (OUTH)
                            *(unsigned*)((__half*)Cout + (size_t)(rt + 8) * Nc + gc) =
                                pack_h2(acc[mi][ni][2], acc[mi][ni][3]);
                        else
                            *(float2*)((float*)Cout + (size_t)(rt + 8) * Nc + gc) =
                                make_float2(acc[mi][ni][2], acc[mi][ni][3]);
                    }
                }
            }
        }
    } else {
        __shared__ float csum[64];
        __shared__ float csq[64];
        if (tid < 64) { csum[tid] = 0.f; csq[tid] = 0.f; }
        __syncthreads();
#pragma unroll
        for (int ni = 0; ni < 4; ni++) {
            int cl = wn * 32 + ni * 8 + 2 * t;
            int gc = col0 + cl;
            if (gc >= Nc) continue;
            float b0 = bias[gc], b1 = bias[gc + 1];
            float s0 = 0.f, s1 = 0.f, q0 = 0.f, q1 = 0.f;
#pragma unroll
            for (int mi = 0; mi < 2; mi++) {
                int rt = row0 + wm * 32 + mi * 16 + g;
                if (rt < M) {
                    float v0 = acc[mi][ni][0] + b0;
                    float v1 = acc[mi][ni][1] + b1;
                    if (OUTH)
                        *(unsigned*)((__half*)Cout + (size_t)rt * Nc + gc) = pack_h2(v0, v1);
                    else
                        *(float2*)((float*)Cout + (size_t)rt * Nc + gc) = make_float2(v0, v1);
                    s0 += v0; s1 += v1; q0 += v0 * v0; q1 += v1 * v1;
                }
                if (rt + 8 < M) {
                    float v2 = acc[mi][ni][2] + b0;
                    float v3 = acc[mi][ni][3] + b1;
                    if (OUTH)
                        *(unsigned*)((__half*)Cout + (size_t)(rt + 8) * Nc + gc) = pack_h2(v2, v3);
                    else
                        *(float2*)((float*)Cout + (size_t)(rt + 8) * Nc + gc) = make_float2(v2, v3);
                    s0 += v2; s1 += v3; q0 += v2 * v2; q1 += v3 * v3;
                }
            }
            atomicAdd(&csum[cl], s0);
            atomicAdd(&csum[cl + 1], s1);
            atomicAdd(&csq[cl], q0);
            atomicAdd(&csq[cl + 1], q1);
        }
        __syncthreads();
        if (tid < 64 && col0 + tid < Nc) {
            atomicAdd(&bnsum[col0 + tid], csum[tid]);
            atomicAdd(&bnsq[col0 + tid], csq[tid]);
        }
    }
}

// ---------------- BN finalize: scale/shift from stats, then re-zero stats ----------------
__global__ void k_bn_finalize(const float* __restrict__ g, const float* __restrict__ be,
                              int d, float invN, float* __restrict__ bn,
                              float* __restrict__ scale, float* __restrict__ shift) {
    int t = threadIdx.x;
    float s = bn[t], q = bn[256 + t];
    if (t < d) {
        float mu  = s * invN;
        float var = q * invN - mu * mu;
        float rstd = rsqrtf(fmaxf(var, 0.f) + 1e-5f);
        float sc = g[t] * rstd;
        scale[t] = sc;
        shift[t] = be[t] - mu * sc;
    }
    bn[t] = 0.f;
    bn[256 + t] = 0.f;
}

// ---------------- edge head: 2 edges per warp, half input, fused affine+relu ----------------
__global__ __launch_bounds__(256) void k_edge_out(
    const __half* __restrict__ conv, const int* __restrict__ src, const int* __restrict__ dst,
    const float* __restrict__ scale, const float* __restrict__ shift,
    const float* __restrict__ fcw, const float* __restrict__ fcb,
    float* __restrict__ out, int E)
{
    int warp = (blockIdx.x * blockDim.x + threadIdx.x) >> 5;
    int lane = threadIdx.x & 31;
    int half = lane >> 4;
    int l16  = lane & 15;
    int eid = warp * 2 + half;
    if (eid >= E) return;
    int s = src[eid], d = dst[eid];
    const __half2* rs = (const __half2*)(conv + (size_t)s * 32);
    const __half2* rd = (const __half2*)(conv + (size_t)d * 32);
    int f = 2 * l16;
    float2 a = __half22float2(__ldg(rs + l16));
    float2 b = __half22float2(__ldg(rd + l16));
    float scx = scale[f], scy = scale[f + 1];
    float shx = shift[f], shy = shift[f + 1];
    a.x = fmaxf(a.x * scx + shx, 0.f);
    a.y = fmaxf(a.y * scy + shy, 0.f);
    b.x = fmaxf(b.x * scx + shx, 0.f);
    b.y = fmaxf(b.y * scy + shy, 0.f);
    float v = a.x * b.x * fcw[f] + a.y * b.y * fcw[f + 1];
#pragma unroll
    for (int o = 8; o; o >>= 1) v += __shfl_xor_sync(0xffffffffu, v, o);
    if (l16 == 0) out[eid] = 1.f / (1.f + expf(-(v + fcb[0])));
}

// ---------------- host ----------------
extern "C" void kernel_launch(void* const* d_in, const int* in_sizes, int n_in,
                              void* d_out, int out_size)
{
    const float* x0 = (const float*)d_in[0];
    const void* ei = d_in[1];
    const float *Wl[5], *bl[5], *gl[5], *bel[5];
    for (int l = 0; l < 5; l++) {
        Wl[l]  = (const float*)d_in[2 + 4 * l];
        bl[l]  = (const float*)d_in[3 + 4 * l];
        gl[l]  = (const float*)d_in[4 + 4 * l];
        bel[l] = (const float*)d_in[5 + 4 * l];
    }
    const float* fcw = (const float*)d_in[22];
    const float* fcb = (const float*)d_in[23];
    float* out = (float*)d_out;
    const int n = NN, E = NE;
    (void)in_sizes; (void)n_in; (void)out_size;

    float *bufA, *bufB, *bufC, *di, *dis, *bn, *scale, *shift;
    __half* bufH;
    int *src, *dst, *cnt, *rowptr, *woff;
    int2* csre;
    cudaGetSymbolAddress((void**)&bufA,  g_bufA);
    cudaGetSymbolAddress((void**)&bufB,  g_bufB);
    cudaGetSymbolAddress((void**)&bufC,  g_bufC);
    cudaGetSymbolAddress((void**)&bufH,  g_bufH);
    cudaGetSymbolAddress((void**)&src,   g_src);
    cudaGetSymbolAddress((void**)&dst,   g_dst);
    cudaGetSymbolAddress((void**)&cnt,   g_cnt);
    cudaGetSymbolAddress((void**)&rowptr,g_rowptr);
    cudaGetSymbolAddress((void**)&woff,  g_woff);
    cudaGetSymbolAddress((void**)&csre,  g_csre);
    cudaGetSymbolAddress((void**)&di,    g_di);
    cudaGetSymbolAddress((void**)&dis,   g_dis);
    cudaGetSymbolAddress((void**)&bn,    g_bn);
    cudaGetSymbolAddress((void**)&scale, g_scale);
    cudaGetSymbolAddress((void**)&shift, g_shift);

    __half* hA = (__half*)bufA;   // reused half tensors
    __half* hB = (__half*)bufB;
    __half* hC = (__half*)bufC;

    int aggBlocks = (n + 7) / 8;
    int rowBlocks = (n + 127) / 128;
    float invN = 1.0f / (float)n;

    k_prep_edges<<<2048, 256>>>(ei, src, dst, cnt, E, n);
    k_scan_deg<<<1, 1024>>>(cnt, rowptr, woff, di, dis, n);
    k_csr<<<2048, 256>>>(src, dst, dis, woff, csre, E);

    // x0 -> half
    k_f2h<<<1024, 256>>>(x0, bufH, n * 128 / 4);

    // L0: S0h = aggh(x0h) -> hA ; GEMM16 S0h@W0+b0 -> conv0h = hB (stats) ; finalize
    k_aggh<128, false, false><<<aggBlocks, 256>>>(bufH, hA, rowptr, csre, di, n,
                                                  nullptr, nullptr, nullptr, nullptr, nullptr);
    k_gemm16<true, false, true><<<dim3(2, rowBlocks), 256>>>(hA, Wl[0], hB, n, 128, 128,
                                                             nullptr, nullptr, bl[0], bn, bn + 256);
    k_bn_finalize<<<1, 256>>>(gl[0], bel[0], 128, invN, bn, scale, shift);

    // L1: S1h = aggh(act(conv0h)) -> hA ; GEMM16 S1h@W1+b1 -> conv1h = hC (stats) ; finalize
    k_aggh<128, false, true><<<aggBlocks, 256>>>(hB, hA, rowptr, csre, di, n,
                                                 scale, shift, nullptr, nullptr, nullptr);
    k_gemm16<true, false, true><<<dim3(4, rowBlocks), 256>>>(hA, Wl[1], hC, n, 128, 256,
                                                             nullptr, nullptr, bl[1], bn, bn + 256);
    k_bn_finalize<<<1, 256>>>(gl[1], bel[1], 256, invN, bn, scale, shift);

    // L2: GEMM16 act(conv1h)@W2 -> h2h = hA ; aggh h2h + b2 -> conv2h = hB (stats) ; finalize
    k_gemm16<false, true, true><<<dim3(2, rowBlocks), 256>>>(hC, Wl[2], hA, n, 256, 128,
                                                             scale, shift, nullptr, nullptr, nullptr);
    k_aggh<128, true, false><<<aggBlocks, 256>>>(hA, hB, rowptr, csre, di, n,
                                                 nullptr, nullptr, bl[2], bn, bn + 256);
    k_bn_finalize<<<1, 256>>>(gl[2], bel[2], 128, invN, bn, scale, shift);

    // L3: GEMM16 act(conv2h)@W3 -> h3h = hA ; aggh h3h + b3 -> conv3h = hC (stats) ; finalize
    k_gemm16<false, true, true><<<dim3(1, rowBlocks), 256>>>(hB, Wl[3], hA, n, 128, 64,
                                                             scale, shift, nullptr, nullptr, nullptr);
    k_aggh<64, true, false><<<aggBlocks, 256>>>(hA, hC, rowptr, csre, di, n,
                                                nullptr, nullptr, bl[3], bn, bn + 256);
    k_bn_finalize<<<1, 256>>>(gl[3], bel[3], 64, invN, bn, scale, shift);

    // L4: GEMM16 act(conv3h)@W4 -> h4 fp32 = bufA ; agg32 h4 + b4 -> conv4h = bufH ; finalize
    k_gemm16<false, true, false><<<dim3(1, rowBlocks), 256>>>(hC, Wl[4], bufA, n, 64, 32,
                                                              scale, shift, nullptr, nullptr, nullptr);
    k_agg32<<<aggBlocks, 256>>>(bufA, bufH, rowptr, csre, di, n, bl[4], bn, bn + 256);
    k_bn_finalize<<<1, 256>>>(gl[4], bel[4], 32, invN, bn, scale, shift);

    // edge head
    int edgeBlocks = (E / 2 + 7) / 8;
    k_edge_out<<<edgeBlocks, 256>>>(bufH, src, dst, scale, shift, fcw, fcb, out, E);
}